// round 10
// baseline (speedup 1.0000x reference)
#include <cuda_runtime.h>
#include <stdint.h>

// GINEConv: out[n] = (1+eps)*node_feat[n] + sum_{e: dst[e]==n} relu(node_feat[src[e]] + edge_feat[e])
// N=50000, E=1600000, D=32 (f32). Indices int32.
//
// Single-pass: init out with eps-residual, then stream edges; each finished
// message row goes into out[dst] via red.global.add.v4.f32 (fire-and-forget).
// R10: consecutive 4-edge-per-thread ownership so indices load as int4
// (8 scalar index LDGs -> 2 vector LDGs per warp-quad), no per-edge predicates
// on the full-quad fast path, launch_bounds(256,4) (best measured residency).

#define DF 32

__global__ void k_init(const float4* __restrict__ node_feat,
                       const float* __restrict__ eps,
                       float4* __restrict__ out,
                       int n4) {
    int i = blockIdx.x * blockDim.x + threadIdx.x;
    if (i >= n4) return;
    float k = 1.0f + eps[0];
    float4 v = node_feat[i];
    out[i] = make_float4(k * v.x, k * v.y, k * v.z, k * v.w);
}

// warp = 16 edges; lane = g*8 + f. Thread (g) owns 4 CONSECUTIVE edges
// [warp*16 + g*4, +4). Index loads are int4; feature loads front-batched.
__global__ void __launch_bounds__(256, 4)
k_edge(const float4* __restrict__ node_feat,
       const float4* __restrict__ edge_feat,
       const int* __restrict__ src,
       const int* __restrict__ dst,
       float4* __restrict__ out,
       int E) {
    int warp = (blockIdx.x * blockDim.x + threadIdx.x) >> 5;
    int lane = threadIdx.x & 31;
    int f = lane & 7;
    int g = lane >> 3;

    int quad = warp * 4 + g;        // int4 index into src/dst
    int base = quad * 4;            // first edge of this thread
    if (base >= E) return;

    if (base + 3 < E) {
        // ---- fast path: full quad, no per-edge predicates ----
        int4 s4 = __ldg((const int4*)src + quad);
        int4 d4 = __ldg((const int4*)dst + quad);
        int s[4] = {s4.x, s4.y, s4.z, s4.w};
        int d[4] = {d4.x, d4.y, d4.z, d4.w};

        float4 ef[4], nf[4];
        #pragma unroll
        for (int u = 0; u < 4; u++)
            ef[u] = __ldcs(edge_feat + (size_t)(base + u) * 8 + f);  // streaming
        #pragma unroll
        for (int u = 0; u < 4; u++)
            nf[u] = __ldg(node_feat + (size_t)s[u] * 8 + f);         // L2 gather

        #pragma unroll
        for (int u = 0; u < 4; u++) {
            float mx = fmaxf(ef[u].x + nf[u].x, 0.f);
            float my = fmaxf(ef[u].y + nf[u].y, 0.f);
            float mz = fmaxf(ef[u].z + nf[u].z, 0.f);
            float mw = fmaxf(ef[u].w + nf[u].w, 0.f);
            float4* p = out + (size_t)d[u] * 8 + f;
            asm volatile("red.global.add.v4.f32 [%0], {%1, %2, %3, %4};"
                         :: "l"(p), "f"(mx), "f"(my), "f"(mz), "f"(mw)
                         : "memory");
        }
    } else {
        // ---- tail: per-edge guarded (cold; E % 16 == 0 makes this unreachable) ----
        for (int u = 0; u < 4; u++) {
            int e = base + u;
            if (e >= E) break;
            int s = __ldg(src + e);
            int d = __ldg(dst + e);
            float4 ef = __ldcs(edge_feat + (size_t)e * 8 + f);
            float4 nf = __ldg(node_feat + (size_t)s * 8 + f);
            float mx = fmaxf(ef.x + nf.x, 0.f);
            float my = fmaxf(ef.y + nf.y, 0.f);
            float mz = fmaxf(ef.z + nf.z, 0.f);
            float mw = fmaxf(ef.w + nf.w, 0.f);
            float4* p = out + (size_t)d * 8 + f;
            asm volatile("red.global.add.v4.f32 [%0], {%1, %2, %3, %4};"
                         :: "l"(p), "f"(mx), "f"(my), "f"(mz), "f"(mw)
                         : "memory");
        }
    }
}

extern "C" void kernel_launch(void* const* d_in, const int* in_sizes, int n_in,
                              void* d_out, int out_size) {
    const float4* node_feat = (const float4*)d_in[0];  // [N, 32] f32
    const float4* edge_feat = (const float4*)d_in[1];  // [E, 32] f32
    const float*  eps       = (const float*)d_in[2];   // [1]
    const int*    src       = (const int*)d_in[3];     // [E] int32
    const int*    dst       = (const int*)d_in[4];     // [E] int32
    float4* out = (float4*)d_out;

    int N = in_sizes[0] / DF;   // 50000
    int E = in_sizes[3];        // 1600000

    // 1) residual init (same stream => ordered before reductions)
    int n4 = N * 8;
    k_init<<<(n4 + 255) / 256, 256>>>(node_feat, eps, out, n4);

    // 2) edge stream + vector-atomic scatter, 16 edges per warp
    long long warps = ((long long)E + 15) / 16;
    long long threads = warps * 32;
    k_edge<<<(int)((threads + 255) / 256), 256>>>(node_feat, edge_feat, src, dst, out, E);
}

// round 11
// speedup vs baseline: 1.0155x; 1.0155x over previous
#include <cuda_runtime.h>
#include <stdint.h>

// GINEConv: out[n] = (1+eps)*node_feat[n] + sum_{e: dst[e]==n} relu(node_feat[src[e]] + edge_feat[e])
// N=50000, E=1600000, D=32 (f32). Indices int32.
//
// Single-pass: init out with eps-residual, then stream edges; each finished
// message row goes into out[dst] via red.global.add.v4.f32 (fire-and-forget).
// Converged design: k_edge is pinned at the chip's LTS/atomic floor (~49us);
// this round locks in the best-measured config (R8: strided 4 edges/thread,
// lb(256,4)) and strips all per-edge predicates on the E%16==0 fast path.

#define DF 32

__global__ void k_init(const float4* __restrict__ node_feat,
                       const float* __restrict__ eps,
                       float4* __restrict__ out,
                       int n4) {
    int i = blockIdx.x * blockDim.x + threadIdx.x;
    if (i >= n4) return;
    float k = 1.0f + eps[0];
    float4 v = node_feat[i];
    out[i] = make_float4(k * v.x, k * v.y, k * v.z, k * v.w);
}

// warp = 16 edges; lane = g*8 + f. Thread owns edges base+g+4u, u=0..3
// (strided ownership: index loads coalesce across the 4 subgroups).
// All loads front-batched; REDs fire-and-forget.
template <bool FULL>
__global__ void __launch_bounds__(256, 4)
k_edge(const float4* __restrict__ node_feat,
       const float4* __restrict__ edge_feat,
       const int* __restrict__ src,
       const int* __restrict__ dst,
       float4* __restrict__ out,
       int E) {
    int warp = (blockIdx.x * blockDim.x + threadIdx.x) >> 5;
    int lane = threadIdx.x & 31;
    int f = lane & 7;
    int g = lane >> 3;

    int base = warp * 16 + g;
    if (!FULL && base >= E) return;

    int ec[4];
    #pragma unroll
    for (int u = 0; u < 4; u++) {
        int e = base + 4 * u;
        ec[u] = FULL ? e : ((e < E) ? e : base);   // FULL: no clamp at all
    }

    // ---- front-batched index loads (broadcast within 8-lane subgroup) ----
    int s[4], d[4];
    #pragma unroll
    for (int u = 0; u < 4; u++) {
        s[u] = __ldg(src + ec[u]);
        d[u] = __ldg(dst + ec[u]);
    }

    // ---- front-batched feature loads: 8 independent 16B loads ----
    float4 ef[4], nf[4];
    #pragma unroll
    for (int u = 0; u < 4; u++)
        ef[u] = __ldcs(edge_feat + (size_t)ec[u] * 8 + f);   // streaming, no reuse
    #pragma unroll
    for (int u = 0; u < 4; u++)
        nf[u] = __ldg(node_feat + (size_t)s[u] * 8 + f);     // L2-resident gather

    // ---- compute + fire-and-forget vector reductions ----
    #pragma unroll
    for (int u = 0; u < 4; u++) {
        if (FULL || base + 4 * u < E) {
            float mx = fmaxf(ef[u].x + nf[u].x, 0.f);
            float my = fmaxf(ef[u].y + nf[u].y, 0.f);
            float mz = fmaxf(ef[u].z + nf[u].z, 0.f);
            float mw = fmaxf(ef[u].w + nf[u].w, 0.f);
            float4* p = out + (size_t)d[u] * 8 + f;
            asm volatile("red.global.add.v4.f32 [%0], {%1, %2, %3, %4};"
                         :: "l"(p), "f"(mx), "f"(my), "f"(mz), "f"(mw)
                         : "memory");
        }
    }
}

extern "C" void kernel_launch(void* const* d_in, const int* in_sizes, int n_in,
                              void* d_out, int out_size) {
    const float4* node_feat = (const float4*)d_in[0];  // [N, 32] f32
    const float4* edge_feat = (const float4*)d_in[1];  // [E, 32] f32
    const float*  eps       = (const float*)d_in[2];   // [1]
    const int*    src       = (const int*)d_in[3];     // [E] int32
    const int*    dst       = (const int*)d_in[4];     // [E] int32
    float4* out = (float4*)d_out;

    int N = in_sizes[0] / DF;   // 50000
    int E = in_sizes[3];        // 1600000

    // 1) residual init (same stream => ordered before reductions)
    int n4 = N * 8;
    k_init<<<(n4 + 255) / 256, 256>>>(node_feat, eps, out, n4);

    // 2) edge stream + vector-atomic scatter, 16 edges per warp
    long long warps = ((long long)E + 15) / 16;
    long long threads = warps * 32;
    int blocks = (int)((threads + 255) / 256);
    if (E % 16 == 0 && (warps * 16 == (long long)E)) {
        k_edge<true><<<blocks, 256>>>(node_feat, edge_feat, src, dst, out, E);
    } else {
        k_edge<false><<<blocks, 256>>>(node_feat, edge_feat, src, dst, out, E);
    }
}